// round 2
// baseline (speedup 1.0000x reference)
#include <cuda_runtime.h>
#include <cstddef>

#define NN 50000
#define EE 800000
#define ENE (EE + NN)

// -------- scratch (static device globals; no allocation) --------
__device__ float g_bufA[NN * 256];   // GEMM output h per layer
__device__ float g_bufB[NN * 256];   // aggregation accumulator / next-layer input
__device__ float g_as[NN * 4];
__device__ float g_ad[NN * 4];
__device__ float g_denom[NN * 4];
__device__ unsigned g_menc[NN * 4];
__device__ float g_pool[64];
__device__ int g_is64;

// -------- edge_index dtype detection: int64 stored little-endian has zero high words --------
__global__ void detect_kernel(const int* __restrict__ ei32)
{
    __shared__ int sh[256];
    int acc = 0;
    for (int i = threadIdx.x; i < 65536; i += 256)
        acc |= ei32[2 * i + 1];
    sh[threadIdx.x] = acc;
    __syncthreads();
    for (int o = 128; o; o >>= 1) {
        if (threadIdx.x < o) sh[threadIdx.x] |= sh[threadIdx.x + o];
        __syncthreads();
    }
    if (threadIdx.x == 0) g_is64 = (sh[0] == 0) ? 1 : 0;
}

__device__ __forceinline__ void load_edge(const int* __restrict__ ei32, int e, int is64,
                                          int& s, int& d)
{
    if (e < EE) {
        if (is64) { s = ei32[2 * e]; d = ei32[2 * (EE + e)]; }
        else      { s = ei32[e];     d = ei32[EE + e]; }
        s = min(max(s, 0), NN - 1);
        d = min(max(d, 0), NN - 1);
    } else {
        s = d = e - EE;
    }
}

// -------- SGEMM: C[M,Nc] = A[M,K] @ W[K,Nc], fp32, 64x64 tile, 4x4/thread --------
__global__ __launch_bounds__(256) void sgemm_kernel(
    const float* __restrict__ A, const float* __restrict__ W,
    float* __restrict__ C, int M, int K, int Nc)
{
    __shared__ float As[64][17];
    __shared__ float Ws[16][68];
    int tid = threadIdx.x;
    int bm = blockIdx.y * 64, bn = blockIdx.x * 64;
    int ty = tid >> 4, tx = tid & 15;
    int r0 = ty * 4, c0 = tx * 4;
    float acc[4][4] = {};

    int am = tid >> 2;           // A-tile row (0..63)
    int ak = (tid & 3) * 4;      // A-tile k offset (0..12)
    int wk = tid >> 4;           // W-tile k row (0..15)
    int wn = (tid & 15) * 4;     // W-tile col offset

    for (int k0 = 0; k0 < K; k0 += 16) {
        float4 av = make_float4(0.f, 0.f, 0.f, 0.f);
        if (bm + am < M)
            av = *(const float4*)(A + (size_t)(bm + am) * K + k0 + ak);
        As[am][ak + 0] = av.x; As[am][ak + 1] = av.y;
        As[am][ak + 2] = av.z; As[am][ak + 3] = av.w;

        float4 wv = *(const float4*)(W + (size_t)(k0 + wk) * Nc + bn + wn);
        Ws[wk][wn + 0] = wv.x; Ws[wk][wn + 1] = wv.y;
        Ws[wk][wn + 2] = wv.z; Ws[wk][wn + 3] = wv.w;
        __syncthreads();

        #pragma unroll
        for (int kk = 0; kk < 16; kk++) {
            float a[4];
            #pragma unroll
            for (int i = 0; i < 4; i++) a[i] = As[r0 + i][kk];
            float4 b4 = *(const float4*)&Ws[kk][c0];
            float b[4] = {b4.x, b4.y, b4.z, b4.w};
            #pragma unroll
            for (int i = 0; i < 4; i++)
                #pragma unroll
                for (int j = 0; j < 4; j++)
                    acc[i][j] += a[i] * b[j];
        }
        __syncthreads();
    }
    #pragma unroll
    for (int i = 0; i < 4; i++) {
        int row = bm + r0 + i;
        if (row < M) {
            #pragma unroll
            for (int j = 0; j < 4; j++)
                C[(size_t)row * Nc + bn + c0 + j] = acc[i][j];
        }
    }
}

// -------- zero accumulator + denom + encoded-max --------
__global__ void init_kernel(float* __restrict__ acc, float* __restrict__ denom,
                            unsigned* __restrict__ menc, int total, int nh)
{
    int idx = blockIdx.x * blockDim.x + threadIdx.x;
    if (idx < total) acc[idx] = 0.f;
    if (idx < nh) { denom[idx] = 0.f; menc[idx] = 0u; }
}

// -------- alpha_s / alpha_d dots: one warp per (node, head) --------
template <int H>
__global__ void alpha_kernel(const float* __restrict__ h,
                             const float* __restrict__ a_s, const float* __restrict__ a_d,
                             float* __restrict__ as_out, float* __restrict__ ad_out)
{
    int gtid = blockIdx.x * blockDim.x + threadIdx.x;
    int warp = gtid >> 5;
    int lane = threadIdx.x & 31;
    if (warp >= NN * H) return;
    int n = warp / H, hh = warp % H;
    const float* row = h + (size_t)n * (H * 64) + hh * 64;
    float v0 = row[lane], v1 = row[lane + 32];
    float s1 = v0 * a_s[hh * 64 + lane] + v1 * a_s[hh * 64 + lane + 32];
    float s2 = v0 * a_d[hh * 64 + lane] + v1 * a_d[hh * 64 + lane + 32];
    #pragma unroll
    for (int o = 16; o; o >>= 1) {
        s1 += __shfl_down_sync(0xffffffffu, s1, o);
        s2 += __shfl_down_sync(0xffffffffu, s2, o);
    }
    if (lane == 0) { as_out[warp] = s1; ad_out[warp] = s2; }
}

// order-preserving uint encoding for float max
__device__ __forceinline__ unsigned fenc(float f) {
    unsigned u = __float_as_uint(f);
    return (u & 0x80000000u) ? ~u : (u | 0x80000000u);
}
__device__ __forceinline__ float fdec(unsigned e) {
    return (e & 0x80000000u) ? __uint_as_float(e & 0x7FFFFFFFu)
                             : __uint_as_float(~e);
}

// -------- edge pass A: segment max of leaky_relu(as[src]+ad[dst]) --------
template <int H>
__global__ void edge_max_kernel(const int* __restrict__ ei32,
                                const float* __restrict__ as_, const float* __restrict__ ad_,
                                unsigned* __restrict__ menc)
{
    int idx = blockIdx.x * blockDim.x + threadIdx.x;
    if (idx >= ENE * H) return;
    int e = idx / H, hh = idx % H;
    int is64 = g_is64;
    int s, d;
    load_edge(ei32, e, is64, s, d);
    float x = as_[s * H + hh] + ad_[d * H + hh];
    x = x > 0.f ? x : 0.2f * x;
    atomicMax(&menc[d * H + hh], fenc(x));
}

// -------- edge pass B: one warp per edge; accumulate ex*h[src] and denom --------
template <int H>
__global__ __launch_bounds__(256) void edge_acc_kernel(
    const int* __restrict__ ei32,
    const float* __restrict__ as_, const float* __restrict__ ad_,
    const unsigned* __restrict__ menc, float* __restrict__ denom,
    const float* __restrict__ hsrc, float* __restrict__ acc)
{
    const int F = H * 64;
    const int VEC = F / 32;  // 8 (H=4) or 2 (H=1) floats per lane
    int gtid = blockIdx.x * blockDim.x + threadIdx.x;
    int e = gtid >> 5;
    int lane = threadIdx.x & 31;
    if (e >= ENE) return;
    int is64 = g_is64;
    int s, d;
    load_edge(ei32, e, is64, s, d);
    int off = lane * VEC;
    int hh = off >> 6;
    float x = as_[s * H + hh] + ad_[d * H + hh];
    x = x > 0.f ? x : 0.2f * x;
    float m = fdec(menc[d * H + hh]);
    float ex = __expf(x - m);
    if ((off & 63) == 0) atomicAdd(&denom[d * H + hh], ex);
    const float* hp = hsrc + (size_t)s * F + off;
    float* ap = acc + (size_t)d * F + off;
    if constexpr (VEC == 8) {
        float4 v0 = *(const float4*)hp;
        float4 v1 = *(const float4*)(hp + 4);
        asm volatile("red.global.add.v4.f32 [%0], {%1,%2,%3,%4};" ::
                     "l"(ap), "f"(ex * v0.x), "f"(ex * v0.y),
                     "f"(ex * v0.z), "f"(ex * v0.w) : "memory");
        asm volatile("red.global.add.v4.f32 [%0], {%1,%2,%3,%4};" ::
                     "l"(ap + 4), "f"(ex * v1.x), "f"(ex * v1.y),
                     "f"(ex * v1.z), "f"(ex * v1.w) : "memory");
    } else {
        float2 v = *(const float2*)hp;
        asm volatile("red.global.add.v2.f32 [%0], {%1,%2};" ::
                     "l"(ap), "f"(ex * v.x), "f"(ex * v.y) : "memory");
    }
}

// -------- normalize: out = acc/denom + b (+ optional relu), in place --------
template <int H>
__global__ void norm_kernel(float* __restrict__ acc, const float* __restrict__ denom,
                            const float* __restrict__ b, int relu)
{
    const int F = H * 64;
    int idx = blockIdx.x * blockDim.x + threadIdx.x;
    if (idx >= NN * F) return;
    int n = idx / F, j = idx % F;
    int hh = j >> 6;
    float v = acc[idx] / (denom[n * H + hh] + 1e-16f) + b[j];
    if (relu) v = v > 0.f ? v : 0.f;
    acc[idx] = v;
}

// -------- mean pool + head --------
__global__ void zero_pool_kernel(float* __restrict__ g) { g[threadIdx.x] = 0.f; }

__global__ void reduce_kernel(const float* __restrict__ h, float* __restrict__ g)
{
    int col = threadIdx.x & 63;
    float s = 0.f;
    for (int r = blockIdx.x * 4 + (threadIdx.x >> 6); r < NN; r += gridDim.x * 4)
        s += h[(size_t)r * 64 + col];
    atomicAdd(&g[col], s);
}

__global__ void head_kernel(const float* __restrict__ g, const float* __restrict__ hw,
                            const float* __restrict__ hb, float* __restrict__ out)
{
    int j = threadIdx.x;  // 64
    float s = 0.f;
    const float inv = 1.f / (float)NN;
    #pragma unroll 8
    for (int c = 0; c < 64; c++)
        s += (g[c] * inv) * hw[c * 64 + j];
    out[j] = s + hb[j];
}

// -------- host orchestration --------
static void run_gemm(const float* A, const float* W, float* C, int M, int K, int Nc) {
    dim3 grid(Nc / 64, (M + 63) / 64);
    sgemm_kernel<<<grid, 256>>>(A, W, C, M, K, Nc);
}

template <int H>
static void run_layer(const float* in, int K, const float* W,
                      const float* a_s, const float* a_d, const float* b,
                      const int* ei32, float* hbuf, float* outbuf,
                      float* as_, float* ad_, float* den, unsigned* menc, int relu)
{
    const int F = H * 64;
    run_gemm(in, W, hbuf, NN, K, F);
    int tot = NN * F;
    init_kernel<<<(tot + 255) / 256, 256>>>(outbuf, den, menc, tot, NN * H);
    int warps = NN * H;
    alpha_kernel<H><<<(warps * 32 + 255) / 256, 256>>>(hbuf, a_s, a_d, as_, ad_);
    edge_max_kernel<H><<<(ENE * H + 255) / 256, 256>>>(ei32, as_, ad_, menc);
    edge_acc_kernel<H><<<(ENE * 32 + 255) / 256, 256>>>(ei32, as_, ad_, menc, den, hbuf, outbuf);
    norm_kernel<H><<<(tot + 255) / 256, 256>>>(outbuf, den, b, relu);
}

extern "C" void kernel_launch(void* const* d_in, const int* in_sizes, int n_in,
                              void* d_out, int out_size)
{
    (void)in_sizes; (void)n_in; (void)out_size;
    const float* x   = (const float*)d_in[0];
    const int*   ei  = (const int*)d_in[1];
    const float* W0  = (const float*)d_in[2];
    const float* a0s = (const float*)d_in[3];
    const float* a0d = (const float*)d_in[4];
    const float* b0  = (const float*)d_in[5];
    const float* W1  = (const float*)d_in[6];
    const float* a1s = (const float*)d_in[7];
    const float* a1d = (const float*)d_in[8];
    const float* b1  = (const float*)d_in[9];
    const float* W2  = (const float*)d_in[10];
    const float* a2s = (const float*)d_in[11];
    const float* a2d = (const float*)d_in[12];
    const float* b2  = (const float*)d_in[13];
    const float* hw  = (const float*)d_in[14];
    const float* hb  = (const float*)d_in[15];
    float* out = (float*)d_out;

    float *bufA, *bufB, *as_, *ad_, *den, *pool;
    unsigned* menc;
    cudaGetSymbolAddress((void**)&bufA, g_bufA);
    cudaGetSymbolAddress((void**)&bufB, g_bufB);
    cudaGetSymbolAddress((void**)&as_,  g_as);
    cudaGetSymbolAddress((void**)&ad_,  g_ad);
    cudaGetSymbolAddress((void**)&den,  g_denom);
    cudaGetSymbolAddress((void**)&menc, g_menc);
    cudaGetSymbolAddress((void**)&pool, g_pool);

    detect_kernel<<<1, 256>>>(ei);

    // Layer 0: x[N,128] -> bufB[N,256] (relu)
    run_layer<4>(x, 128, W0, a0s, a0d, b0, ei, bufA, bufB, as_, ad_, den, menc, 1);
    // Layer 1: bufB[N,256] -> bufB[N,256] (relu); GEMM out in bufA
    run_layer<4>(bufB, 256, W1, a1s, a1d, b1, ei, bufA, bufB, as_, ad_, den, menc, 1);
    // Layer 2: bufB[N,256] -> bufB[N,64] (no relu)
    run_layer<1>(bufB, 256, W2, a2s, a2d, b2, ei, bufA, bufB, as_, ad_, den, menc, 0);

    zero_pool_kernel<<<1, 64>>>(pool);
    reduce_kernel<<<256, 256>>>(bufB, pool);
    head_kernel<<<1, 64>>>(pool, hw, hb, out);
}

// round 5
// speedup vs baseline: 1.6436x; 1.6436x over previous
#include <cuda_runtime.h>
#include <cstddef>

#define NN 50000
#define EE 800000
#define ENE (EE + NN)

// -------- scratch (static device globals; no allocation) --------
__device__ float g_bufA[NN * 256];   // GEMM output h per layer
__device__ float g_bufB[NN * 256];   // aggregation output / next-layer input
__device__ float g_as[NN * 4];
__device__ float g_ad[NN * 4];
__device__ float g_pool[64];
__device__ int g_is64;
__device__ int g_src[ENE];
__device__ int g_dst[ENE];
__device__ int g_cnt[NN];
__device__ int g_off[NN + 1];
__device__ int g_fill[NN];
__device__ int g_csrc[ENE];

// -------- edge_index dtype detection --------
__global__ void detect_kernel(const int* __restrict__ ei32)
{
    __shared__ int sh[256];
    int acc = 0;
    for (int i = threadIdx.x; i < 65536; i += 256)
        acc |= ei32[2 * i + 1];
    sh[threadIdx.x] = acc;
    __syncthreads();
    for (int o = 128; o; o >>= 1) {
        if (threadIdx.x < o) sh[threadIdx.x] |= sh[threadIdx.x + o];
        __syncthreads();
    }
    if (threadIdx.x == 0) g_is64 = (sh[0] == 0) ? 1 : 0;
}

// -------- CSR build --------
__global__ void zero_cnt_kernel()
{
    int i = blockIdx.x * blockDim.x + threadIdx.x;
    if (i < NN) g_cnt[i] = 0;
}

__global__ void decode_kernel(const int* __restrict__ ei32)
{
    int e = blockIdx.x * blockDim.x + threadIdx.x;
    if (e >= ENE) return;
    int s, d;
    if (e < EE) {
        if (g_is64) { s = ei32[2 * e]; d = ei32[2 * (EE + e)]; }
        else        { s = ei32[e];     d = ei32[EE + e]; }
        s = min(max(s, 0), NN - 1);
        d = min(max(d, 0), NN - 1);
    } else {
        s = d = e - EE;
    }
    g_src[e] = s;
    g_dst[e] = d;
    atomicAdd(&g_cnt[d], 1);
}

__global__ __launch_bounds__(1024) void scan_kernel()
{
    __shared__ int sm[1024];
    const int CH = 49;  // 1024*49 = 50176 >= NN
    int t = threadIdx.x;
    int base = t * CH;
    int sum = 0;
    for (int i = 0; i < CH; i++) {
        int idx = base + i;
        if (idx < NN) sum += g_cnt[idx];
    }
    sm[t] = sum;
    __syncthreads();
    for (int off = 1; off < 1024; off <<= 1) {
        int v = (t >= off) ? sm[t - off] : 0;
        __syncthreads();
        sm[t] += v;
        __syncthreads();
    }
    int run = (t > 0) ? sm[t - 1] : 0;
    for (int i = 0; i < CH; i++) {
        int idx = base + i;
        if (idx < NN) {
            g_off[idx] = run;
            g_fill[idx] = run;
            run += g_cnt[idx];
        }
    }
    if (t == 1023) g_off[NN] = run;
}

__global__ void scatter_kernel()
{
    int e = blockIdx.x * blockDim.x + threadIdx.x;
    if (e >= ENE) return;
    int d = g_dst[e];
    int pos = atomicAdd(&g_fill[d], 1);
    g_csrc[pos] = g_src[e];
}

// -------- SGEMM: C[M,Nc] = A[M,K] @ W[K,Nc], 128xBN tile, BK=16 --------
template <int BN>
__global__ __launch_bounds__(256) void sgemm_kernel(
    const float* __restrict__ A, const float* __restrict__ W,
    float* __restrict__ C, int M, int K, int Nc)
{
    constexpr int BM = 128, BK = 16;
    constexpr int TN = BN / 16;  // 8 (BN=128) or 4 (BN=64)
    __shared__ float As[BK][BM + 4];
    __shared__ float Bs[BK][BN + 4];
    int tid = threadIdx.x;
    int bm = blockIdx.y * BM, bn = blockIdx.x * BN;
    int tx = tid & 15, ty = tid >> 4;

    float acc[8][TN] = {};

    int arow = tid >> 2;          // 0..63 (+64 second)
    int ak = (tid & 3) * 4;

    for (int k0 = 0; k0 < K; k0 += BK) {
        // A tile (transposed store)
        #pragma unroll
        for (int h = 0; h < 2; h++) {
            int r = arow + h * 64;
            float4 v = make_float4(0.f, 0.f, 0.f, 0.f);
            if (bm + r < M)
                v = *(const float4*)(A + (size_t)(bm + r) * K + k0 + ak);
            As[ak + 0][r] = v.x; As[ak + 1][r] = v.y;
            As[ak + 2][r] = v.z; As[ak + 3][r] = v.w;
        }
        // B tile
        if (BN == 128) {
            int brow = tid >> 5;           // 0..7 (+8)
            int bcol = (tid & 31) * 4;
            #pragma unroll
            for (int h = 0; h < 2; h++) {
                float4 v = *(const float4*)(W + (size_t)(k0 + brow + h * 8) * Nc + bn + bcol);
                *(float4*)&Bs[brow + h * 8][bcol] = v;
            }
        } else {
            int brow = tid >> 4;           // 0..15
            int bcol = (tid & 15) * 4;
            float4 v = *(const float4*)(W + (size_t)(k0 + brow) * Nc + bn + bcol);
            *(float4*)&Bs[brow][bcol] = v;
        }
        __syncthreads();

        #pragma unroll
        for (int kk = 0; kk < BK; kk++) {
            float4 a0 = *(const float4*)&As[kk][ty * 4];
            float4 a1 = *(const float4*)&As[kk][ty * 4 + 64];
            float av[8] = {a0.x, a0.y, a0.z, a0.w, a1.x, a1.y, a1.z, a1.w};
            float bv[TN];
            float4 b0 = *(const float4*)&Bs[kk][tx * 4];
            bv[0] = b0.x; bv[1] = b0.y; bv[2] = b0.z; bv[3] = b0.w;
            if (BN == 128) {
                float4 b1 = *(const float4*)&Bs[kk][tx * 4 + 64];
                bv[4] = b1.x; bv[5] = b1.y; bv[6] = b1.z; bv[7] = b1.w;
            }
            #pragma unroll
            for (int i = 0; i < 8; i++)
                #pragma unroll
                for (int j = 0; j < TN; j++)
                    acc[i][j] += av[i] * bv[j];
        }
        __syncthreads();
    }

    #pragma unroll
    for (int i = 0; i < 8; i++) {
        int r = bm + ty * 4 + (i < 4 ? i : 60 + i);
        if (r < M) {
            *(float4*)(C + (size_t)r * Nc + bn + tx * 4) =
                make_float4(acc[i][0], acc[i][1], acc[i][2], acc[i][3]);
            if (BN == 128)
                *(float4*)(C + (size_t)r * Nc + bn + tx * 4 + 64) =
                    make_float4(acc[i][4], acc[i][5], acc[i][6], acc[i][7]);
        }
    }
}

// -------- alpha_s / alpha_d dots: one warp per (node, head) --------
template <int H>
__global__ void alpha_kernel(const float* __restrict__ h,
                             const float* __restrict__ a_s, const float* __restrict__ a_d,
                             float* __restrict__ as_out, float* __restrict__ ad_out)
{
    int gtid = blockIdx.x * blockDim.x + threadIdx.x;
    int warp = gtid >> 5;
    int lane = threadIdx.x & 31;
    if (warp >= NN * H) return;
    int n = warp / H, hh = warp % H;
    const float* row = h + (size_t)n * (H * 64) + hh * 64;
    float v0 = row[lane], v1 = row[lane + 32];
    float s1 = v0 * a_s[hh * 64 + lane] + v1 * a_s[hh * 64 + lane + 32];
    float s2 = v0 * a_d[hh * 64 + lane] + v1 * a_d[hh * 64 + lane + 32];
    #pragma unroll
    for (int o = 16; o; o >>= 1) {
        s1 += __shfl_down_sync(0xffffffffu, s1, o);
        s2 += __shfl_down_sync(0xffffffffu, s2, o);
    }
    if (lane == 0) { as_out[warp] = s1; ad_out[warp] = s2; }
}

// -------- aggregation: one warp per dst node, CSR walk (max pass + acc pass) --------
template <int H>
__global__ __launch_bounds__(256) void aggregate_kernel(
    const float* __restrict__ as_, const float* __restrict__ ad_,
    const float* __restrict__ h,
    const float* __restrict__ b, float* __restrict__ outp, int relu)
{
    const int F = H * 64;
    const int VEC = F / 32;  // 8 (H=4) or 2 (H=1)
    int gtid = blockIdx.x * blockDim.x + threadIdx.x;
    int node = gtid >> 5;
    int lane = threadIdx.x & 31;
    if (node >= NN) return;
    int hh = (lane * VEC) >> 6;
    float adv = ad_[node * H + hh];
    int i0 = g_off[node], i1 = g_off[node + 1];

    // pass 1: per-(node,head) max of leaky_relu(as[src]+ad[node])
    float m = -1e30f;
    for (int i = i0; i < i1; i++) {
        float x = as_[g_csrc[i] * H + hh] + adv;
        x = x > 0.f ? x : 0.2f * x;
        m = fmaxf(m, x);
    }

    // pass 2: accumulate
    float acc[VEC] = {};
    float den = 0.f;
    for (int i = i0; i < i1; i++) {
        int s = g_csrc[i];
        float x = as_[s * H + hh] + adv;
        x = x > 0.f ? x : 0.2f * x;
        float ex = __expf(x - m);
        den += ex;
        const float* hp = h + (size_t)s * F + lane * VEC;
        if (VEC == 8) {
            float4 v0 = *(const float4*)hp;
            float4 v1 = *(const float4*)(hp + 4);
            acc[0] += ex * v0.x; acc[1] += ex * v0.y;
            acc[2] += ex * v0.z; acc[3] += ex * v0.w;
            acc[4] += ex * v1.x; acc[5] += ex * v1.y;
            acc[6] += ex * v1.z; acc[7] += ex * v1.w;
        } else {
            float2 v = *(const float2*)hp;
            acc[0] += ex * v.x; acc[1] += ex * v.y;
        }
    }
    float inv = 1.f / (den + 1e-16f);
    float* op = outp + (size_t)node * F + lane * VEC;
    #pragma unroll
    for (int j = 0; j < VEC; j++) {
        float v = acc[j] * inv + b[lane * VEC + j];
        if (relu) v = v > 0.f ? v : 0.f;
        op[j] = v;
    }
}

// -------- mean pool + head --------
__global__ void zero_pool_kernel(float* __restrict__ g) { g[threadIdx.x] = 0.f; }

__global__ void reduce_kernel(const float* __restrict__ h, float* __restrict__ g)
{
    int col = threadIdx.x & 63;
    float s = 0.f;
    for (int r = blockIdx.x * 4 + (threadIdx.x >> 6); r < NN; r += gridDim.x * 4)
        s += h[(size_t)r * 64 + col];
    atomicAdd(&g[col], s);
}

__global__ void head_kernel(const float* __restrict__ g, const float* __restrict__ hw,
                            const float* __restrict__ hb, float* __restrict__ out)
{
    int j = threadIdx.x;  // 64
    float s = 0.f;
    const float inv = 1.f / (float)NN;
    #pragma unroll 8
    for (int c = 0; c < 64; c++)
        s += (g[c] * inv) * hw[c * 64 + j];
    out[j] = s + hb[j];
}

// -------- host orchestration --------
template <int H>
static void run_layer(const float* in, int K, const float* W,
                      const float* a_s, const float* a_d, const float* b,
                      float* hbuf, float* outbuf,
                      float* as_, float* ad_, int relu)
{
    const int F = H * 64;
    if (F == 256) {
        dim3 grid(2, (NN + 127) / 128);
        sgemm_kernel<128><<<grid, 256>>>(in, W, hbuf, NN, K, F);
    } else {
        dim3 grid(1, (NN + 127) / 128);
        sgemm_kernel<64><<<grid, 256>>>(in, W, hbuf, NN, K, F);
    }
    int warps = NN * H;
    alpha_kernel<H><<<(warps * 32 + 255) / 256, 256>>>(hbuf, a_s, a_d, as_, ad_);
    aggregate_kernel<H><<<(NN * 32 + 255) / 256, 256>>>(as_, ad_, hbuf, b, outbuf, relu);
}

extern "C" void kernel_launch(void* const* d_in, const int* in_sizes, int n_in,
                              void* d_out, int out_size)
{
    (void)in_sizes; (void)n_in; (void)out_size;
    const float* x   = (const float*)d_in[0];
    const int*   ei  = (const int*)d_in[1];
    const float* W0  = (const float*)d_in[2];
    const float* a0s = (const float*)d_in[3];
    const float* a0d = (const float*)d_in[4];
    const float* b0  = (const float*)d_in[5];
    const float* W1  = (const float*)d_in[6];
    const float* a1s = (const float*)d_in[7];
    const float* a1d = (const float*)d_in[8];
    const float* b1  = (const float*)d_in[9];
    const float* W2  = (const float*)d_in[10];
    const float* a2s = (const float*)d_in[11];
    const float* a2d = (const float*)d_in[12];
    const float* b2  = (const float*)d_in[13];
    const float* hw  = (const float*)d_in[14];
    const float* hb  = (const float*)d_in[15];
    float* out = (float*)d_out;

    float *bufA, *bufB, *as_, *ad_, *pool;
    cudaGetSymbolAddress((void**)&bufA, g_bufA);
    cudaGetSymbolAddress((void**)&bufB, g_bufB);
    cudaGetSymbolAddress((void**)&as_,  g_as);
    cudaGetSymbolAddress((void**)&ad_,  g_ad);
    cudaGetSymbolAddress((void**)&pool, g_pool);

    detect_kernel<<<1, 256>>>(ei);
    zero_cnt_kernel<<<(NN + 255) / 256, 256>>>();
    decode_kernel<<<(ENE + 255) / 256, 256>>>(ei);
    scan_kernel<<<1, 1024>>>();
    scatter_kernel<<<(ENE + 255) / 256, 256>>>();

    // Layer 0: x[N,128] -> bufB[N,256] (relu)
    run_layer<4>(x, 128, W0, a0s, a0d, b0, bufA, bufB, as_, ad_, 1);
    // Layer 1: bufB -> bufB (relu); GEMM out in bufA
    run_layer<4>(bufB, 256, W1, a1s, a1d, b1, bufA, bufB, as_, ad_, 1);
    // Layer 2: bufB[N,256] -> bufB[N,64] (no relu)
    run_layer<1>(bufB, 256, W2, a2s, a2d, b2, bufA, bufB, as_, ad_, 0);

    zero_pool_kernel<<<1, 64>>>(pool);
    reduce_kernel<<<256, 256>>>(bufB, pool);
    head_kernel<<<1, 64>>>(pool, hw, hb, out);
}

// round 8
// speedup vs baseline: 2.5727x; 1.5653x over previous
#include <cuda_runtime.h>
#include <cstddef>

#define NN 50000
#define EE 800000
#define ENE (EE + NN)
#define SCAN_B 196   // ceil(NN/256)

// -------- scratch (static device globals; no allocation) --------
__device__ float g_bufA[NN * 256];   // GEMM output h per layer
__device__ float g_bufB[NN * 256];   // aggregation output / next-layer input
__device__ float g_as[NN * 4];
__device__ float g_ad[NN * 4];
__device__ float g_pool[64];
__device__ int g_is64;
__device__ int g_src[ENE];
__device__ int g_dst[ENE];
__device__ int g_cnt[NN];
__device__ int g_off[NN + 1];
__device__ int g_fill[NN];
__device__ int g_csrc[ENE];
__device__ int g_bsum[256];
__device__ int g_boff[256];

// -------- edge_index dtype detection --------
__global__ void detect_kernel(const int* __restrict__ ei32)
{
    __shared__ int sh[256];
    int acc = 0;
    for (int i = threadIdx.x; i < 65536; i += 256)
        acc |= ei32[2 * i + 1];
    sh[threadIdx.x] = acc;
    __syncthreads();
    for (int o = 128; o; o >>= 1) {
        if (threadIdx.x < o) sh[threadIdx.x] |= sh[threadIdx.x + o];
        __syncthreads();
    }
    if (threadIdx.x == 0) g_is64 = (sh[0] == 0) ? 1 : 0;
}

// -------- CSR build --------
__global__ void zero_cnt_kernel()
{
    int i = blockIdx.x * blockDim.x + threadIdx.x;
    if (i < NN) g_cnt[i] = 0;
}

__global__ void decode_kernel(const int* __restrict__ ei32)
{
    int e = blockIdx.x * blockDim.x + threadIdx.x;
    if (e >= ENE) return;
    int s, d;
    if (e < EE) {
        if (g_is64) { s = ei32[2 * e]; d = ei32[2 * (EE + e)]; }
        else        { s = ei32[e];     d = ei32[EE + e]; }
        s = min(max(s, 0), NN - 1);
        d = min(max(d, 0), NN - 1);
    } else {
        s = d = e - EE;
    }
    g_src[e] = s;
    g_dst[e] = d;
    atomicAdd(&g_cnt[d], 1);
}

// 3-stage parallel exclusive scan of g_cnt -> g_off
__global__ void block_sum_kernel()
{
    __shared__ int sh[256];
    int t = threadIdx.x;
    int i = blockIdx.x * 256 + t;
    sh[t] = (i < NN) ? g_cnt[i] : 0;
    __syncthreads();
    for (int o = 128; o; o >>= 1) {
        if (t < o) sh[t] += sh[t + o];
        __syncthreads();
    }
    if (t == 0) g_bsum[blockIdx.x] = sh[0];
}

__global__ void scan_bsum_kernel()
{
    __shared__ int sh[256];
    int t = threadIdx.x;
    sh[t] = (t < SCAN_B) ? g_bsum[t] : 0;
    __syncthreads();
    for (int o = 1; o < 256; o <<= 1) {
        int u = (t >= o) ? sh[t - o] : 0;
        __syncthreads();
        sh[t] += u;
        __syncthreads();
    }
    g_boff[t] = t ? sh[t - 1] : 0;
    if (t == SCAN_B - 1) g_off[NN] = sh[t];
}

__global__ void scan_final_kernel()
{
    __shared__ int sh[256];
    int t = threadIdx.x;
    int i = blockIdx.x * 256 + t;
    int v = (i < NN) ? g_cnt[i] : 0;
    sh[t] = v;
    __syncthreads();
    for (int o = 1; o < 256; o <<= 1) {
        int u = (t >= o) ? sh[t - o] : 0;
        __syncthreads();
        sh[t] += u;
        __syncthreads();
    }
    if (i < NN) {
        int ex = sh[t] - v + g_boff[blockIdx.x];
        g_off[i] = ex;
        g_fill[i] = ex;
    }
}

__global__ void scatter_kernel()
{
    int e = blockIdx.x * blockDim.x + threadIdx.x;
    if (e >= ENE) return;
    int d = g_dst[e];
    int pos = atomicAdd(&g_fill[d], 1);
    g_csrc[pos] = g_src[e];
}

// -------- zero alpha accumulators --------
__global__ void zero_alpha_kernel(float* __restrict__ as_, float* __restrict__ ad_, int nh)
{
    int i = blockIdx.x * blockDim.x + threadIdx.x;
    if (i < nh) { as_[i] = 0.f; ad_[i] = 0.f; }
}

// -------- TF32 tensor-core GEMM + fused alpha epilogue --------
// C[M,Nc] = A[M,K] @ W[K,Nc]; BM=128, BN=64 (one head), BK=32.
// 8 warps as 2(M) x 4(N); warp tile 64x16; mma m16n8k8.
// Epilogue also accumulates as[n,h] = sum_c h*a_s, ad[n,h] = sum_c h*a_d via atomics.
__device__ __forceinline__ unsigned f2tf32(float f)
{
    unsigned u;
    asm("cvt.rna.tf32.f32 %0, %1;" : "=r"(u) : "f"(f));
    return u;
}

__global__ __launch_bounds__(256) void gemm_tf32_kernel(
    const float* __restrict__ A, const float* __restrict__ W,
    float* __restrict__ C, int M, int K, int Nc,
    const float* __restrict__ a_s, const float* __restrict__ a_d,
    float* __restrict__ as_out, float* __restrict__ ad_out, int H)
{
    __shared__ unsigned As[128][36];  // [m][k], padded
    __shared__ unsigned Bs[32][68];   // [k][n], padded

    int tid = threadIdx.x;
    int bm = blockIdx.y * 128, bn = blockIdx.x * 64;
    int head = bn >> 6;
    int wid = tid >> 5, lane = tid & 31;
    int warpM = wid & 1, warpN = wid >> 1;       // 2 x 4
    int g = lane >> 2, t4 = lane & 3;

    float acc[4][2][4] = {};                     // [mfrag][nfrag][reg]

    int arow = tid >> 1;                 // 0..127
    int akc = (tid & 1) * 16;            // 0 or 16
    int brow = tid >> 3;                 // 0..31
    int bnc = (tid & 7) * 8;             // 0..56

    for (int k0 = 0; k0 < K; k0 += 32) {
        bool av = (bm + arow) < M;
        const float* ap = A + (size_t)(bm + arow) * K + k0 + akc;
        #pragma unroll
        for (int i = 0; i < 4; i++) {
            float4 v = av ? *(const float4*)(ap + i * 4)
                          : make_float4(0.f, 0.f, 0.f, 0.f);
            As[arow][akc + i * 4 + 0] = f2tf32(v.x);
            As[arow][akc + i * 4 + 1] = f2tf32(v.y);
            As[arow][akc + i * 4 + 2] = f2tf32(v.z);
            As[arow][akc + i * 4 + 3] = f2tf32(v.w);
        }
        const float* wp = W + (size_t)(k0 + brow) * Nc + bn + bnc;
        #pragma unroll
        for (int i = 0; i < 2; i++) {
            float4 v = *(const float4*)(wp + i * 4);
            Bs[brow][bnc + i * 4 + 0] = f2tf32(v.x);
            Bs[brow][bnc + i * 4 + 1] = f2tf32(v.y);
            Bs[brow][bnc + i * 4 + 2] = f2tf32(v.z);
            Bs[brow][bnc + i * 4 + 3] = f2tf32(v.w);
        }
        __syncthreads();

        #pragma unroll
        for (int ks = 0; ks < 4; ks++) {
            int kb = ks * 8;
            unsigned b0[2], b1[2];
            #pragma unroll
            for (int nf = 0; nf < 2; nf++) {
                int nb = warpN * 16 + nf * 8 + g;
                b0[nf] = Bs[kb + t4][nb];
                b1[nf] = Bs[kb + t4 + 4][nb];
            }
            #pragma unroll
            for (int mf = 0; mf < 4; mf++) {
                int rb = warpM * 64 + mf * 16;
                unsigned a0 = As[rb + g][kb + t4];
                unsigned a1 = As[rb + g + 8][kb + t4];
                unsigned a2 = As[rb + g][kb + t4 + 4];
                unsigned a3 = As[rb + g + 8][kb + t4 + 4];
                #pragma unroll
                for (int nf = 0; nf < 2; nf++) {
                    asm volatile(
                        "mma.sync.aligned.m16n8k8.row.col.f32.tf32.tf32.f32 "
                        "{%0,%1,%2,%3}, {%4,%5,%6,%7}, {%8,%9}, {%0,%1,%2,%3};"
                        : "+f"(acc[mf][nf][0]), "+f"(acc[mf][nf][1]),
                          "+f"(acc[mf][nf][2]), "+f"(acc[mf][nf][3])
                        : "r"(a0), "r"(a1), "r"(a2), "r"(a3),
                          "r"(b0[nf]), "r"(b1[nf]));
                }
            }
        }
        __syncthreads();
    }

    // store C + fused alpha partials
    #pragma unroll
    for (int mf = 0; mf < 4; mf++) {
        int r0 = bm + warpM * 64 + mf * 16 + g;
        float s0 = 0.f, d0 = 0.f, s1 = 0.f, d1 = 0.f;  // rows r0, r0+8
        #pragma unroll
        for (int nf = 0; nf < 2; nf++) {
            int cc = warpN * 16 + nf * 8 + t4 * 2;   // in-head col (0..62)
            float w_s0 = a_s[head * 64 + cc],     w_s1 = a_s[head * 64 + cc + 1];
            float w_d0 = a_d[head * 64 + cc],     w_d1 = a_d[head * 64 + cc + 1];
            s0 += acc[mf][nf][0] * w_s0 + acc[mf][nf][1] * w_s1;
            d0 += acc[mf][nf][0] * w_d0 + acc[mf][nf][1] * w_d1;
            s1 += acc[mf][nf][2] * w_s0 + acc[mf][nf][3] * w_s1;
            d1 += acc[mf][nf][2] * w_d0 + acc[mf][nf][3] * w_d1;

            int col = bn + cc;
            if (r0 < M)
                *(float2*)(C + (size_t)r0 * Nc + col) =
                    make_float2(acc[mf][nf][0], acc[mf][nf][1]);
            if (r0 + 8 < M)
                *(float2*)(C + (size_t)(r0 + 8) * Nc + col) =
                    make_float2(acc[mf][nf][2], acc[mf][nf][3]);
        }
        // reduce across the 4 lanes of the quad (same g, different t4 = different cols)
        #pragma unroll
        for (int o = 1; o <= 2; o <<= 1) {
            s0 += __shfl_xor_sync(0xffffffffu, s0, o);
            d0 += __shfl_xor_sync(0xffffffffu, d0, o);
            s1 += __shfl_xor_sync(0xffffffffu, s1, o);
            d1 += __shfl_xor_sync(0xffffffffu, d1, o);
        }
        if (t4 == 0) {
            if (r0 < M) {
                atomicAdd(&as_out[r0 * H + head], s0);
                atomicAdd(&ad_out[r0 * H + head], d0);
            }
            if (r0 + 8 < M) {
                atomicAdd(&as_out[(r0 + 8) * H + head], s1);
                atomicAdd(&ad_out[(r0 + 8) * H + head], d1);
            }
        }
    }
}

// -------- aggregation: one warp per dst node, online-softmax CSR walk --------
template <int H>
__global__ __launch_bounds__(256) void aggregate_kernel(
    const float* __restrict__ as_, const float* __restrict__ ad_,
    const float* __restrict__ h,
    const float* __restrict__ b, float* __restrict__ outp, int relu)
{
    const int F = H * 64;
    const int VEC = F / 32;  // 8 (H=4) or 2 (H=1)
    int gtid = blockIdx.x * blockDim.x + threadIdx.x;
    int node = gtid >> 5;
    int lane = threadIdx.x & 31;
    if (node >= NN) return;
    int hh = (lane * VEC) >> 6;
    float adv = ad_[node * H + hh];
    int i0 = g_off[node], i1 = g_off[node + 1];

    float m = -1e30f, den = 0.f;
    float acc[VEC] = {};
    for (int i = i0; i < i1; i++) {
        int s = g_csrc[i];
        float x = as_[s * H + hh] + adv;
        x = x > 0.f ? x : 0.2f * x;
        if (x > m) {
            float r = __expf(m - x);
            den *= r;
            #pragma unroll
            for (int j = 0; j < VEC; j++) acc[j] *= r;
            m = x;
        }
        float ex = __expf(x - m);
        den += ex;
        const float* hp = h + (size_t)s * F + lane * VEC;
        if (VEC == 8) {
            float4 v0 = *(const float4*)hp;
            float4 v1 = *(const float4*)(hp + 4);
            acc[0] += ex * v0.x; acc[1] += ex * v0.y;
            acc[2] += ex * v0.z; acc[3] += ex * v0.w;
            acc[4] += ex * v1.x; acc[5] += ex * v1.y;
            acc[6] += ex * v1.z; acc[7] += ex * v1.w;
        } else {
            float2 v = *(const float2*)hp;
            acc[0] += ex * v.x; acc[1] += ex * v.y;
        }
    }
    float inv = 1.f / (den + 1e-16f);
    float* op = outp + (size_t)node * F + lane * VEC;
    #pragma unroll
    for (int j = 0; j < VEC; j++) {
        float v = acc[j] * inv + b[lane * VEC + j];
        if (relu) v = v > 0.f ? v : 0.f;
        op[j] = v;
    }
}

// -------- mean pool + head --------
__global__ void zero_pool_kernel(float* __restrict__ g) { g[threadIdx.x] = 0.f; }

__global__ void reduce_kernel(const float* __restrict__ h, float* __restrict__ g)
{
    int col = threadIdx.x & 63;
    float s = 0.f;
    for (int r = blockIdx.x * 4 + (threadIdx.x >> 6); r < NN; r += gridDim.x * 4)
        s += h[(size_t)r * 64 + col];
    atomicAdd(&g[col], s);
}

__global__ void head_kernel(const float* __restrict__ g, const float* __restrict__ hw,
                            const float* __restrict__ hb, float* __restrict__ out)
{
    int j = threadIdx.x;  // 64
    float s = 0.f;
    const float inv = 1.f / (float)NN;
    #pragma unroll 8
    for (int c = 0; c < 64; c++)
        s += (g[c] * inv) * hw[c * 64 + j];
    out[j] = s + hb[j];
}

// -------- host orchestration --------
template <int H>
static void run_layer(const float* in, int K, const float* W,
                      const float* a_s, const float* a_d, const float* b,
                      float* hbuf, float* outbuf,
                      float* as_, float* ad_, int relu)
{
    const int F = H * 64;
    zero_alpha_kernel<<<(NN * H + 255) / 256, 256>>>(as_, ad_, NN * H);
    dim3 grid(F / 64, (NN + 127) / 128);
    gemm_tf32_kernel<<<grid, 256>>>(in, W, hbuf, NN, K, F, a_s, a_d, as_, ad_, H);
    aggregate_kernel<H><<<(NN * 32 + 255) / 256, 256>>>(as_, ad_, hbuf, b, outbuf, relu);
}

extern "C" void kernel_launch(void* const* d_in, const int* in_sizes, int n_in,
                              void* d_out, int out_size)
{
    (void)in_sizes; (void)n_in; (void)out_size;
    const float* x   = (const float*)d_in[0];
    const int*   ei  = (const int*)d_in[1];
    const float* W0  = (const float*)d_in[2];
    const float* a0s = (const float*)d_in[3];
    const float* a0d = (const float*)d_in[4];
    const float* b0  = (const float*)d_in[5];
    const float* W1  = (const float*)d_in[6];
    const float* a1s = (const float*)d_in[7];
    const float* a1d = (const float*)d_in[8];
    const float* b1  = (const float*)d_in[9];
    const float* W2  = (const float*)d_in[10];
    const float* a2s = (const float*)d_in[11];
    const float* a2d = (const float*)d_in[12];
    const float* b2  = (const float*)d_in[13];
    const float* hw  = (const float*)d_in[14];
    const float* hb  = (const float*)d_in[15];
    float* out = (float*)d_out;

    float *bufA, *bufB, *as_, *ad_, *pool;
    cudaGetSymbolAddress((void**)&bufA, g_bufA);
    cudaGetSymbolAddress((void**)&bufB, g_bufB);
    cudaGetSymbolAddress((void**)&as_,  g_as);
    cudaGetSymbolAddress((void**)&ad_,  g_ad);
    cudaGetSymbolAddress((void**)&pool, g_pool);

    detect_kernel<<<1, 256>>>(ei);
    zero_cnt_kernel<<<(NN + 255) / 256, 256>>>();
    decode_kernel<<<(ENE + 255) / 256, 256>>>(ei);
    block_sum_kernel<<<SCAN_B, 256>>>();
    scan_bsum_kernel<<<1, 256>>>();
    scan_final_kernel<<<SCAN_B, 256>>>();
    scatter_kernel<<<(ENE + 255) / 256, 256>>>();

    // Layer 0: x[N,128] -> bufB[N,256] (relu)
    run_layer<4>(x, 128, W0, a0s, a0d, b0, bufA, bufB, as_, ad_, 1);
    // Layer 1: bufB -> bufB (relu); GEMM out in bufA
    run_layer<4>(bufB, 256, W1, a1s, a1d, b1, bufA, bufB, as_, ad_, 1);
    // Layer 2: bufB[N,256] -> bufB[N,64] (no relu)
    run_layer<1>(bufB, 256, W2, a2s, a2d, b2, bufA, bufB, as_, ad_, 0);

    zero_pool_kernel<<<1, 64>>>(pool);
    reduce_kernel<<<256, 256>>>(bufB, pool);
    head_kernel<<<1, 64>>>(pool, hw, hb, out);
}